// round 16
// baseline (speedup 1.0000x reference)
#include <cuda_runtime.h>
#include <cuda_bf16.h>
#include <cstdint>

// MHC layer: B=8192, N=4, C=4096, f32. HBM-bound fusion.
// R16 = R15 (one barrier/row, own-slot discipline, rms-independent hoist)
// + per-thread DECOUPLED depth-2 prefetch: right after pass A drains its
// own smem slots into registers, each thread issues cp.async for row r+2
// into the same slots — no barrier coupling on the load path at all.
// 2 rows of reads in flight per SM; load issue decorrelated from barriers.

#define C_DIM 4096
#define NS 4
#define THREADS 1024            // = C_DIM/4 -> one float4 per stream per thread
#define ROWS_PER_CTA 8
#define EPS 1e-6f
#define ROW_F4 (NS * C_DIM / 4)             // 4096 float4 per row buffer
#define SMEM_BYTES (2 * ROW_F4 * 16)        // 128 KB: two row buffers

__device__ __forceinline__ uint32_t smem_u32(const void* p) {
    uint32_t a;
    asm("{ .reg .u64 t; cvta.to.shared.u64 t, %1; cvt.u32.u64 %0, t; }"
        : "=r"(a) : "l"(p));
    return a;
}

__device__ __forceinline__ void load_row(uint32_t sbuf, const float4* xrow, int t) {
#pragma unroll
    for (int n = 0; n < NS; n++) {
        const int idx = n * THREADS + t;
        asm volatile("cp.async.cg.shared.global [%0], [%1], 16;"
                     :: "r"(sbuf + idx * 16), "l"(xrow + idx));
    }
    asm volatile("cp.async.commit_group;");
}

__global__ __launch_bounds__(THREADS, 1)
void mhc_kernel(const float* __restrict__ x,
                const float* __restrict__ w,
                const float* __restrict__ H_pre,
                const float* __restrict__ H_post,
                const float* __restrict__ H_res,
                float* __restrict__ out)
{
    extern __shared__ float4 sx[];          // [2][ROW_F4]
    __shared__ float4 red4[2][THREADS / 32 / 4];   // [parity][8] = 32 floats
    __shared__ float sp[24];                // [0:4)=hpre [4:8)=hpost [8:24)=P

    const int t = threadIdx.x;
    const int b0 = blockIdx.x * ROWS_PER_CTA;
    const uint32_t sbase = smem_u32(sx);
    const float4* __restrict__ x4 = reinterpret_cast<const float4*>(x);

    // ---- prologue: issue rows b0 (buf0) and b0+1 (buf1) ----
    load_row(sbase,                 x4 + (size_t)b0 * ROW_F4,       t);
    load_row(sbase + ROW_F4 * 16,   x4 + (size_t)(b0 + 1) * ROW_F4, t);

    // ---- thread 0: tiny parameter math into smem while copies fly ----
    if (t == 0) {
#pragma unroll
        for (int n = 0; n < NS; n++) {
            sp[n]     = 1.0f / (1.0f + expf(-H_pre[n]));
            sp[4 + n] = 2.0f / (1.0f + expf(-H_post[n]));
        }
        float P[NS][NS];
#pragma unroll
        for (int i = 0; i < NS; i++)
#pragma unroll
            for (int j = 0; j < NS; j++)
                P[i][j] = expf(H_res[i * NS + j]);
#pragma unroll
        for (int it = 0; it < 3; it++) {
#pragma unroll
            for (int i = 0; i < NS; i++) {
                float inv = 1.0f / (P[i][0] + P[i][1] + P[i][2] + P[i][3] + EPS);
#pragma unroll
                for (int j = 0; j < NS; j++) P[i][j] *= inv;
            }
#pragma unroll
            for (int j = 0; j < NS; j++) {
                float inv = 1.0f / (P[0][j] + P[1][j] + P[2][j] + P[3][j] + EPS);
#pragma unroll
                for (int i = 0; i < NS; i++) P[i][j] *= inv;
            }
        }
#pragma unroll
        for (int i = 0; i < NS; i++)
#pragma unroll
            for (int j = 0; j < NS; j++)
                sp[8 + i * NS + j] = P[i][j];
    }
    __syncthreads();   // params visible (prologue only)

    // ---- params into registers ----
    const float hp0 = sp[0], hp1 = sp[1], hp2 = sp[2], hp3 = sp[3];
    float Pr[NS][NS], hq[NS];
#pragma unroll
    for (int i = 0; i < NS; i++) {
        hq[i] = sp[4 + i];
#pragma unroll
        for (int j = 0; j < NS; j++) Pr[i][j] = sp[8 + i * NS + j];
    }

    const float4 w4 = reinterpret_cast<const float4*>(w)[t];

#pragma unroll 1
    for (int r = 0; r < ROWS_PER_CTA; r++) {
        const int b = b0 + r;
        const int cur = r & 1;
        const int par = r & 1;

        // ---- wait row r complete (row r+1 may still be in flight) ----
        if (r + 1 < ROWS_PER_CTA)
            asm volatile("cp.async.wait_group 1;" ::: "memory");
        else
            asm volatile("cp.async.wait_group 0;" ::: "memory");
        // NO barrier: own-slot discipline.

        const float4* __restrict__ sb = sx + cur * ROW_F4;

        // ---- pass A: drain own slots to regs; gated agg + bf16 rt ----
        const float4 v0 = sb[0 * THREADS + t];
        const float4 v1 = sb[1 * THREADS + t];
        const float4 v2 = sb[2 * THREADS + t];
        const float4 v3 = sb[3 * THREADS + t];

        // ---- decoupled depth-2 prefetch: row r+2 into THIS buffer ----
        // Own slots just consumed; cp.async smem write lands >=234cyc out,
        // LDS above completed in ~29cyc. No cross-thread hazard (own slots).
        if (r + 2 < ROWS_PER_CTA)
            load_row(sbase + cur * (ROW_F4 * 16),
                     x4 + (size_t)(b + 2) * ROW_F4, t);

        float ax = hp0*v0.x + hp1*v1.x + hp2*v2.x + hp3*v3.x;
        float ay = hp0*v0.y + hp1*v1.y + hp2*v2.y + hp3*v3.y;
        float az = hp0*v0.z + hp1*v1.z + hp2*v2.z + hp3*v3.z;
        float aw = hp0*v0.w + hp1*v1.w + hp2*v2.w + hp3*v3.w;
        ax = __bfloat162float(__float2bfloat16(ax));
        ay = __bfloat162float(__float2bfloat16(ay));
        az = __bfloat162float(__float2bfloat16(az));
        aw = __bfloat162float(__float2bfloat16(aw));
        float ss = ax*ax + ay*ay + az*az + aw*aw;

        // ---- hoisted rms-independent work (overlaps the barrier) ----
        float4 o[NS];
#pragma unroll
        for (int i = 0; i < NS; i++) {
            o[i].x = Pr[i][0]*v0.x + Pr[i][1]*v1.x + Pr[i][2]*v2.x + Pr[i][3]*v3.x;
            o[i].y = Pr[i][0]*v0.y + Pr[i][1]*v1.y + Pr[i][2]*v2.y + Pr[i][3]*v3.y;
            o[i].z = Pr[i][0]*v0.z + Pr[i][1]*v1.z + Pr[i][2]*v2.z + Pr[i][3]*v3.z;
            o[i].w = Pr[i][0]*v0.w + Pr[i][1]*v1.w + Pr[i][2]*v2.w + Pr[i][3]*v3.w;
        }
        float4 aw4;
        aw4.x = ax * w4.x; aw4.y = ay * w4.y;
        aw4.z = az * w4.z; aw4.w = aw * w4.w;

        // ---- reduce: warp partials -> ONE barrier -> all-thread sum ----
#pragma unroll
        for (int off = 16; off > 0; off >>= 1)
            ss += __shfl_xor_sync(0xFFFFFFFFu, ss, off);
        if ((t & 31) == 0)
            reinterpret_cast<float*>(red4[par])[t >> 5] = ss;

        __syncthreads();   // the ONE barrier per row

        float4 acc = red4[par][0];
#pragma unroll
        for (int q = 1; q < 8; q++) {
            const float4 p = red4[par][q];
            acc.x += p.x; acc.y += p.y; acc.z += p.z; acc.w += p.w;
        }
        const float inv_rms =
            rsqrtf(((acc.x + acc.y) + (acc.z + acc.w)) * (1.0f / C_DIM) + EPS);

        // ---- minimal tail: o[i] += hq[i]*inv_rms*aw4, float4 stores ----
        float4* __restrict__ outr =
            reinterpret_cast<float4*>(out + (size_t)b * NS * C_DIM);
#pragma unroll
        for (int i = 0; i < NS; i++) {
            const float s = hq[i] * inv_rms;
            float4 oo = o[i];
            oo.x += s * aw4.x;
            oo.y += s * aw4.y;
            oo.z += s * aw4.z;
            oo.w += s * aw4.w;
            outr[i * THREADS + t] = oo;
        }
        // no trailing barrier (own-slot discipline; red4 parity-buffered)
    }
}

extern "C" void kernel_launch(void* const* d_in, const int* in_sizes, int n_in,
                              void* d_out, int out_size)
{
    const float* x      = (const float*)d_in[0];  // [8192, 4, 4096]
    const float* w      = (const float*)d_in[1];  // [4096]
    const float* H_pre  = (const float*)d_in[2];  // [4]
    const float* H_post = (const float*)d_in[3];  // [4]
    const float* H_res  = (const float*)d_in[4];  // [4, 4]
    float* out = (float*)d_out;                   // [8192, 4, 4096]

    cudaFuncSetAttribute(mhc_kernel,
                         cudaFuncAttributeMaxDynamicSharedMemorySize, SMEM_BYTES);

    const int B = in_sizes[0] / (NS * C_DIM);     // 8192
    mhc_kernel<<<B / ROWS_PER_CTA, THREADS, SMEM_BYTES>>>(x, w, H_pre, H_post, H_res, out);
}